// round 11
// baseline (speedup 1.0000x reference)
#include <cuda_runtime.h>
#include <cstdint>

// DAM softmax loss — persistent block-per-row, rolling 256-bit-load pipeline,
// inline target-margin correction.
//   logits = S*costh, except target col: S*(ct - 0.15*exp(1-ct))
//   loss = mean_row( logsumexp(logits_row) - logits_row[target] )
// costh in [0,1) -> S*costh < 15 -> fixed max 15, single pass.
// sm_103a LDG.E.256: each thread streams 32 B/round -> half the LDG count of
// the float4 version. Row = 40000 B = 1250 chunks of 32 B; 256 threads ->
// 5 rounds (last partial: 226 threads). Depth-2 rolling prefetch.

static constexpr int   B_ROWS  = 8192;
static constexpr int   C_COLS  = 10000;
static constexpr int   THREADS = 256;
static constexpr int   NUM_SMS = 148;
static constexpr int   BLOCKS_PER_SM = 8;
static constexpr int   GRID    = NUM_SMS * BLOCKS_PER_SM;    // 1184, one wave
static constexpr int   NCH     = C_COLS / 8;                 // 1250 32B chunks
static constexpr int   ROUNDS  = (NCH + THREADS - 1) / THREADS;  // 5
static constexpr float S_SCALE = 15.0f;
static constexpr float MARGIN_OVER_LAMDA = 0.3f / 2.0f;      // 0.15

__device__ double       g_acc  = 0.0;
__device__ unsigned int g_done = 0u;

__device__ __forceinline__ float ex2_approx(float x) {
    float r;
    asm("ex2.approx.f32 %0, %1;" : "=f"(r) : "f"(x));
    return r;
}

struct f8 { float4 a, b; };

__device__ __forceinline__ f8 ldg256(const float* p) {
    f8 v;
    asm("ld.global.nc.v8.f32 {%0,%1,%2,%3,%4,%5,%6,%7}, [%8];"
        : "=f"(v.a.x), "=f"(v.a.y), "=f"(v.a.z), "=f"(v.a.w),
          "=f"(v.b.x), "=f"(v.b.y), "=f"(v.b.z), "=f"(v.b.w)
        : "l"(p));
    return v;
}

__device__ __forceinline__ f8 sentinel8() {
    f8 v;
    v.a = make_float4(-1.0e4f, -1.0e4f, -1.0e4f, -1.0e4f);
    v.b = v.a;
    return v;
}

__global__ void __launch_bounds__(THREADS, BLOCKS_PER_SM)
dam_loss_v8_kernel(const float* __restrict__ costh,
                   const int* __restrict__ label,
                   float* __restrict__ out) {
    const int tid = threadIdx.x;

    // exp(S*c - 15) = exp2( (S*log2e)*c - 15*log2e )
    const float L2E  = 1.4426950408889634f;
    const float SL2E = S_SCALE * L2E;
    const float BIAS = -S_SCALE * L2E;

    __shared__ float warp_sums[2][THREADS / 32];
    __shared__ float sh_ct2[2];

    int parity = 0;
    for (int row = blockIdx.x; row < B_ROWS; row += GRID, parity ^= 1) {
        // Row base: 40000 B stride, 32B-aligned (40000 % 32 == 0).
        const float* __restrict__ rb = costh + (size_t)row * C_COLS;

        int t = __ldg(&label[row]);
        t = min(max(t, 0), C_COLS - 1);
        const int tch = t >> 3;   // which 32B chunk
        const int tco = t & 7;    // which float within chunk

        // Depth-2 rolling pipeline over 5 rounds (chunk idx = tid + r*256).
        f8 b0 = ldg256(rb + (size_t)tid * 8);              // r=0, always valid
        f8 b1 = ldg256(rb + (size_t)(tid + THREADS) * 8);  // r=1, always valid

        float s0 = 0.0f, s1 = 0.0f, s2 = 0.0f, s3 = 0.0f;

        #pragma unroll
        for (int r = 0; r < ROUNDS; r++) {
            f8 cur = b0;
            b0 = b1;
            // Prefetch for consumption round r+2 (last valid round: 4).
            if (r + 2 < ROUNDS) {
                const int pidx = tid + (r + 2) * THREADS;
                // Only r+2 == 4 is partial (pidx up to 1279 vs NCH=1250).
                b1 = (pidx < NCH) ? ldg256(rb + (size_t)pidx * 8) : sentinel8();
            } else {
                b1 = sentinel8();
            }

            const int idx = tid + r * THREADS;
            if (idx == tch) {      // exactly one thread, one round, per row
                float* f = (tco < 4) ? (&cur.a.x + tco) : (&cur.b.x + (tco - 4));
                const float ct  = *f;
                const float ct2 = ct - MARGIN_OVER_LAMDA * expf(1.0f - ct);
                *f = ct2;
                sh_ct2[parity] = ct2;
            }

            s0 += ex2_approx(fmaf(cur.a.x, SL2E, BIAS));
            s1 += ex2_approx(fmaf(cur.a.y, SL2E, BIAS));
            s2 += ex2_approx(fmaf(cur.a.z, SL2E, BIAS));
            s3 += ex2_approx(fmaf(cur.a.w, SL2E, BIAS));
            s0 += ex2_approx(fmaf(cur.b.x, SL2E, BIAS));
            s1 += ex2_approx(fmaf(cur.b.y, SL2E, BIAS));
            s2 += ex2_approx(fmaf(cur.b.z, SL2E, BIAS));
            s3 += ex2_approx(fmaf(cur.b.w, SL2E, BIAS));
        }

        float s = (s0 + s1) + (s2 + s3);
        #pragma unroll
        for (int off = 16; off; off >>= 1)
            s += __shfl_xor_sync(0xffffffffu, s, off);

        if ((tid & 31) == 0) warp_sums[parity][tid >> 5] = s;
        __syncthreads();

        if (tid == 0) {
            float tot = 0.0f;
            #pragma unroll
            for (int w = 0; w < THREADS / 32; w++) tot += warp_sums[parity][w];
            const float ct2 = sh_ct2[parity];
            // tot already contains the corrected target term.
            const float loss_row = 15.0f + logf(tot) - S_SCALE * ct2;
            atomicAdd(&g_acc, (double)loss_row);   // result unused -> RED
        }
        // Parity double-buffering covers thread 0's lag (it must pass the
        // next same-parity row's __syncthreads before buffers are reused).
    }

    if (tid == 0) {
        __threadfence();
        const unsigned ticket = atomicAdd(&g_done, 1u);
        if (ticket == (unsigned)(GRID - 1)) {
            out[0] = (float)(g_acc * (1.0 / (double)B_ROWS));
            g_acc  = 0.0;
            g_done = 0u;
            __threadfence();
        }
    }
}

extern "C" void kernel_launch(void* const* d_in, const int* in_sizes, int n_in,
                              void* d_out, int out_size) {
    const float* costh = (const float*)d_in[0];
    const int*   label = (const int*)d_in[1];
    float*       out   = (float*)d_out;

    dam_loss_v8_kernel<<<GRID, THREADS>>>(costh, label, out);
}

// round 12
// speedup vs baseline: 1.4628x; 1.4628x over previous
#include <cuda_runtime.h>

// DAM softmax loss — persistent block-per-row, rolling load pipeline,
// inline target-margin correction. R9 structure (best: 53.76us) with
// L2::256B prefetch hints on the streaming loads.
//   logits = S*costh, except target col: S*(ct - 0.15*exp(1-ct))
//   loss = mean_row( logsumexp(logits_row) - logits_row[target] )
// costh in [0,1) -> S*costh < 15 -> fixed max 15, single pass.

static constexpr int   B_ROWS  = 8192;
static constexpr int   C_COLS  = 10000;
static constexpr int   THREADS = 256;
static constexpr int   NUM_SMS = 148;
static constexpr int   BLOCKS_PER_SM = 8;
static constexpr int   GRID    = NUM_SMS * BLOCKS_PER_SM;   // 1184, one wave
static constexpr int   NVEC    = C_COLS / 4;                // 2500
static constexpr int   ROUNDS  = (NVEC + THREADS - 1) / THREADS;  // 10
static constexpr int   DEPTH   = 4;                         // pipeline depth
static constexpr float S_SCALE = 15.0f;
static constexpr float MARGIN_OVER_LAMDA = 0.3f / 2.0f;     // 0.15

__device__ double       g_acc  = 0.0;
__device__ unsigned int g_done = 0u;

__device__ __forceinline__ float ex2_approx(float x) {
    float r;
    asm("ex2.approx.f32 %0, %1;" : "=f"(r) : "f"(x));
    return r;
}

// Streaming 128-bit load, evict-first, with 256B L2 prefetch hint.
__device__ __forceinline__ float4 ldcs256(const float4* p) {
    float4 v;
    asm("ld.global.nc.cs.L2::256B.v4.f32 {%0,%1,%2,%3}, [%4];"
        : "=f"(v.x), "=f"(v.y), "=f"(v.z), "=f"(v.w) : "l"(p));
    return v;
}

// Sentinel: drives ex2 argument hugely negative -> contributes exactly 0.
__device__ __forceinline__ float4 sentinel4() {
    return make_float4(-1.0e4f, -1.0e4f, -1.0e4f, -1.0e4f);
}

__global__ void __launch_bounds__(THREADS, BLOCKS_PER_SM)
dam_loss_pipe_kernel(const float* __restrict__ costh,
                     const int* __restrict__ label,
                     float* __restrict__ out) {
    const int tid = threadIdx.x;

    // exp(S*c - 15) = exp2( (S*log2e)*c - 15*log2e )
    const float L2E  = 1.4426950408889634f;
    const float SL2E = S_SCALE * L2E;
    const float BIAS = -S_SCALE * L2E;

    __shared__ float warp_sums[2][THREADS / 32];
    __shared__ float sh_ct2[2];

    int parity = 0;
    for (int row = blockIdx.x; row < B_ROWS; row += GRID, parity ^= 1) {
        const float4* __restrict__ rp =
            reinterpret_cast<const float4*>(costh + (size_t)row * C_COLS);

        // Target column info (same address for all threads -> broadcast hit).
        int t = __ldg(&label[row]);
        t = min(max(t, 0), C_COLS - 1);
        const int tv = t >> 2;   // which float4
        const int tc = t & 3;    // which component

        // Depth-4 rolling pipeline over 10 rounds.
        // Round r consumes idx = tid + r*256 (loaded DEPTH rounds earlier).
        float4 b0 = ldcs256(&rp[tid]);                 // rounds 0..3: in range
        float4 b1 = ldcs256(&rp[tid + THREADS]);
        float4 b2 = ldcs256(&rp[tid + 2 * THREADS]);
        float4 b3 = ldcs256(&rp[tid + 3 * THREADS]);

        float s0 = 0.0f, s1 = 0.0f, s2 = 0.0f, s3 = 0.0f;

        #pragma unroll
        for (int r = 0; r < ROUNDS; r++) {
            float4 cur = b0;
            b0 = b1; b1 = b2; b2 = b3;
            // Prefetch for consumption round r+DEPTH (last valid: ROUNDS-1).
            if (r + DEPTH < ROUNDS) {
                const int pidx = tid + (r + DEPTH) * THREADS;
                // Only the final prefetch round (pidx up to 2559) is partial.
                b3 = (pidx < NVEC) ? ldcs256(&rp[pidx]) : sentinel4();
            } else {
                b3 = sentinel4();
            }

            const int idx = tid + r * THREADS;
            if (idx == tv) {       // exactly one thread, one round, per row
                float ct = (tc == 0) ? cur.x : (tc == 1) ? cur.y
                          : (tc == 2) ? cur.z : cur.w;
                float ct2 = ct - MARGIN_OVER_LAMDA * expf(1.0f - ct);
                if (tc == 0) cur.x = ct2;
                else if (tc == 1) cur.y = ct2;
                else if (tc == 2) cur.z = ct2;
                else cur.w = ct2;
                sh_ct2[parity] = ct2;
            }

            s0 += ex2_approx(fmaf(cur.x, SL2E, BIAS));
            s1 += ex2_approx(fmaf(cur.y, SL2E, BIAS));
            s2 += ex2_approx(fmaf(cur.z, SL2E, BIAS));
            s3 += ex2_approx(fmaf(cur.w, SL2E, BIAS));
        }

        float s = (s0 + s1) + (s2 + s3);
        #pragma unroll
        for (int off = 16; off; off >>= 1)
            s += __shfl_xor_sync(0xffffffffu, s, off);

        if ((tid & 31) == 0) warp_sums[parity][tid >> 5] = s;
        __syncthreads();

        if (tid == 0) {
            float tot = 0.0f;
            #pragma unroll
            for (int w = 0; w < THREADS / 32; w++) tot += warp_sums[parity][w];
            const float ct2 = sh_ct2[parity];
            // tot already contains the corrected target term.
            const float loss_row = 15.0f + logf(tot) - S_SCALE * ct2;
            atomicAdd(&g_acc, (double)loss_row);   // result unused -> RED
        }
        // Parity double-buffering: next row uses the other buffers, and
        // thread 0 must pass the next row's __syncthreads before any buffer
        // with this parity is written again.
    }

    if (tid == 0) {
        __threadfence();
        const unsigned ticket = atomicAdd(&g_done, 1u);
        if (ticket == (unsigned)(GRID - 1)) {
            out[0] = (float)(g_acc * (1.0 / (double)B_ROWS));
            g_acc  = 0.0;
            g_done = 0u;
            __threadfence();
        }
    }
}

extern "C" void kernel_launch(void* const* d_in, const int* in_sizes, int n_in,
                              void* d_out, int out_size) {
    const float* costh = (const float*)d_in[0];
    const int*   label = (const int*)d_in[1];
    float*       out   = (float*)d_out;

    dam_loss_pipe_kernel<<<GRID, THREADS>>>(costh, label, out);
}